// round 17
// baseline (speedup 1.0000x reference)
#include <cuda_runtime.h>
#include <cstdint>

// ConcatenateMeanMax: out[b] = concat(bond_ft[b], mean(atom[s0],atom[s1]),
//                                     max(atom[s0],atom[s1])), DEG=2 fixed.
//
// v8 (256-bit) pair version: one warp handles bonds {2w, 2w+1}.
//   - bond load: one v8 ld covers both rows (1024B contiguous, full warp)
//   - atom gathers: v8 ld, half-warps duplicate addresses (HW dedup -> 512B)
//   - output: pair block is 3072B contiguous -> exactly 3 full-warp v8 stores
//     with per-half-warp operand select:
//       st0 = [bf0 | mean0], st1 = [max0 | bf1], st2 = [mean1 | max1]
// Policies (measured best): evict_last descriptor on atoms, evict_first on
// bond + output streams. Baseline to beat: 155.3us ncu / 159.8us bench,
// 1.029GB @ 6.63TB/s.

constexpr int D = 128;

struct F8 { float v[8]; };

__device__ __forceinline__ F8 ld8(const float* p, uint64_t pol) {
    F8 r;
    asm volatile("ld.global.nc.L2::cache_hint.v8.b32 {%0,%1,%2,%3,%4,%5,%6,%7}, [%8], %9;"
                 : "=f"(r.v[0]), "=f"(r.v[1]), "=f"(r.v[2]), "=f"(r.v[3]),
                   "=f"(r.v[4]), "=f"(r.v[5]), "=f"(r.v[6]), "=f"(r.v[7])
                 : "l"(p), "l"(pol));
    return r;
}

__device__ __forceinline__ void st8(float* p, const F8& x, uint64_t pol) {
    asm volatile("st.global.L2::cache_hint.v8.b32 [%0], {%1,%2,%3,%4,%5,%6,%7,%8}, %9;"
                 :: "l"(p),
                    "f"(x.v[0]), "f"(x.v[1]), "f"(x.v[2]), "f"(x.v[3]),
                    "f"(x.v[4]), "f"(x.v[5]), "f"(x.v[6]), "f"(x.v[7]),
                    "l"(pol)
                 : "memory");
}

__global__ __launch_bounds__(256)
void concat_mean_max_kernel(const float* __restrict__ atom_ft,
                            const float* __restrict__ bond_ft,
                            const int*  __restrict__ edge_src,
                            float* __restrict__ out,
                            int n_bonds)
{
    const int w    = (blockIdx.x * blockDim.x + threadIdx.x) >> 5;
    const int lane = threadIdx.x & 31;
    const int b0 = w * 2;
    const int b1 = b0 + 1;
    if (b0 >= n_bonds) return;

    uint64_t polL, polF;
    asm("createpolicy.fractional.L2::evict_last.b64 %0, 1.0;"  : "=l"(polL));
    asm("createpolicy.fractional.L2::evict_first.b64 %0, 1.0;" : "=l"(polF));

    if (b1 < n_bonds) {
        // ---- fast pair path ----
        const int4 s = __ldg(&((const int4*)edge_src)[w]);  // {s00,s01,s10,s11}
        const int p = lane >> 4;      // which bond within the pair
        const int j = lane & 15;      // 32B chunk within a 512B row

        // gathers (both half-warps load same chunks; HW dedups to 512B/row)
        const F8 A  = ld8(atom_ft + (long long)s.x * D + j * 8, polL);
        const F8 B  = ld8(atom_ft + (long long)s.y * D + j * 8, polL);
        const F8 C  = ld8(atom_ft + (long long)s.z * D + j * 8, polL);
        const F8 E  = ld8(atom_ft + (long long)s.w * D + j * 8, polL);
        // bond rows b0,b1 contiguous: one 1024B full-warp load
        const F8 BF = ld8(bond_ft + (long long)b0 * D + lane * 8, polF);

        float* base = out + (long long)b0 * (3 * D);   // 3072B pair block
        F8 t;

        // st0: [bf0 | mean0]
        #pragma unroll
        for (int i = 0; i < 8; i++)
            t.v[i] = p ? (A.v[i] + B.v[i]) * 0.5f : BF.v[i];
        st8(base + lane * 8, t, polF);

        // st1: [max0 | bf1]
        #pragma unroll
        for (int i = 0; i < 8; i++)
            t.v[i] = p ? BF.v[i] : fmaxf(A.v[i], B.v[i]);
        st8(base + 256 + lane * 8, t, polF);

        // st2: [mean1 | max1]
        #pragma unroll
        for (int i = 0; i < 8; i++)
            t.v[i] = p ? fmaxf(C.v[i], E.v[i]) : (C.v[i] + E.v[i]) * 0.5f;
        st8(base + 512 + lane * 8, t, polF);
    } else {
        // ---- tail: single bond b0, classic float4 path ----
        const int2 s2 = __ldg(&((const int2*)edge_src)[b0]);
        const float4* atom4 = (const float4*)atom_ft;
        const float4* bond4 = (const float4*)bond_ft;
        const int DV = D / 4;

        const float4 bf = __ldcs(&bond4[(long long)b0 * DV + lane]);
        const float4 a0 = __ldg (&atom4[(long long)s2.x * DV + lane]);
        const float4 a1 = __ldg (&atom4[(long long)s2.y * DV + lane]);

        float4 mean_v, max_v;
        mean_v.x = (a0.x + a1.x) * 0.5f;  max_v.x = fmaxf(a0.x, a1.x);
        mean_v.y = (a0.y + a1.y) * 0.5f;  max_v.y = fmaxf(a0.y, a1.y);
        mean_v.z = (a0.z + a1.z) * 0.5f;  max_v.z = fmaxf(a0.z, a1.z);
        mean_v.w = (a0.w + a1.w) * 0.5f;  max_v.w = fmaxf(a0.w, a1.w);

        float4* orow = (float4*)(out + (long long)b0 * (3 * D));
        __stcs(orow + lane,          bf);
        __stcs(orow + DV + lane,     mean_v);
        __stcs(orow + 2 * DV + lane, max_v);
    }
}

extern "C" void kernel_launch(void* const* d_in, const int* in_sizes, int n_in,
                              void* d_out, int out_size)
{
    const float* atom_ft  = (const float*)d_in[0];   // [N_ATOMS, 128] f32
    const float* bond_ft  = (const float*)d_in[1];   // [N_BONDS, 128] f32
    const int*   edge_src = (const int*)d_in[2];     // [N_BONDS*2] i32
    // d_in[3] = edge_dst (structurally repeat(arange, 2)) -- not needed.

    const int n_bonds = in_sizes[1] / D;

    const int threads = 256;                        // 8 warps -> 16 bonds/block
    const int bonds_per_block = (threads / 32) * 2;
    const int blocks = (n_bonds + bonds_per_block - 1) / bonds_per_block;

    concat_mean_max_kernel<<<blocks, threads>>>(
        atom_ft, bond_ft, edge_src, (float*)d_out, n_bonds);
}